// round 15
// baseline (speedup 1.0000x reference)
#include <cuda_runtime.h>
#include <cuda_fp16.h>
#include <math.h>
#include <stdint.h>

#define B_ 4
#define S_ 4096
#define D_ 4096
#define H_ 128
#define E_ 8
#define M_ (B_*S_)

#define MTILE 64
#define KT 64
#define NCHUNK (D_/KT)        // 64
#define NTH 256
// A planes only in SMEM now (XOR swizzle: chunk16 ^= (row & 7))
#define APL 8192              // 64 rows * 128B
#define OFF_AH 0
#define OFF_AL APL
#define STAGE (2*APL)         // 16384
#define OFF_W2 34048          // past Hs region (64*132*4 = 33792)
#define OFF_B1 (OFF_W2 + H_*E_*4)
#define OFF_B2 (OFF_B1 + H_*4)
#define SMEM_BYTES (OFF_B2 + 64)

#define LO_SCALE 2048.0f
#define LO_INV   (1.0f/2048.0f)

#define NKSG 256              // k16 steps across D
#define PKSTRIDE (NKSG*16*32) // uint2 per plane = 131072

// ---------------- device globals ----------------
// B fragments pre-packed in m16n8k16 col-major fragment order:
// g_Wpk[pl*PKSTRIDE + (ksg*16 + nf)*32 + lane] = {B[h][k]|B[h][k+1]<<16, B[h][k+8]|B[h][k+9]<<16}
// with h = nf*8 + lane/4, k = ksg*16 + 2*(lane%4); B[h][k] = W1[k][h] (hi or lo*2048 fp16)
__device__ __align__(16) uint2 g_Wpk[2 * PKSTRIDE];
__device__ float g_hpart[B_][128][H_];
__device__ float g_task_w[B_][E_];
__device__ float g_alpha;

// ---------------- helpers ----------------
__device__ __forceinline__ unsigned s2u(const void* p) {
    unsigned r;
    asm("{ .reg .u64 t; cvta.to.shared.u64 t, %1; cvt.u32.u64 %0, t; }" : "=r"(r) : "l"(p));
    return r;
}
__device__ __forceinline__ unsigned pkh(float lo, float hi) { // f16x2 {lo, hi}
    unsigned r;
    asm("cvt.rn.f16x2.f32 %0, %1, %2;" : "=r"(r) : "f"(hi), "f"(lo));
    return r;
}
__device__ __forceinline__ void ldmx4(unsigned* r, unsigned a) {
    asm volatile("ldmatrix.sync.aligned.m8n8.x4.shared.b16 {%0,%1,%2,%3}, [%4];"
                 : "=r"(r[0]), "=r"(r[1]), "=r"(r[2]), "=r"(r[3]) : "r"(a));
}
__device__ __forceinline__ void mma16816(float* c, const unsigned* a, const unsigned* b) {
    asm volatile(
        "mma.sync.aligned.m16n8k16.row.col.f32.f16.f16.f32 "
        "{%0,%1,%2,%3}, {%4,%5,%6,%7}, {%8,%9}, {%0,%1,%2,%3};"
        : "+f"(c[0]), "+f"(c[1]), "+f"(c[2]), "+f"(c[3])
        : "r"(a[0]), "r"(a[1]), "r"(a[2]), "r"(a[3]), "r"(b[0]), "r"(b[1]));
}
__device__ __forceinline__ unsigned f16hi_bits(float v) {
    __half hv = __float2half_rn(v);
    return (unsigned)__half_as_ushort(hv);
}

// ---------------- fused prelude: B fragment pack (blocks 0-255) + task partials (256-383) ----------------
__global__ void prelude_kernel(const float* __restrict__ W1,
                               const float* __restrict__ task,
                               const float* __restrict__ TW1) {
    const int bid = blockIdx.x;
    const int t = threadIdx.x;       // 0..511
    if (bid < NKSG) {
        __shared__ float ws[16][128];          // W1[ksg*16 + r][h]
        const int ksg = bid;
#pragma unroll
        for (int i = t; i < 2048; i += 512)
            ((float*)ws)[i] = W1[(size_t)ksg * 2048 + i];   // contiguous, coalesced
        __syncthreads();
        const int nf = t >> 5, lane = t & 31;
        const int h = nf * 8 + (lane >> 2);
        const int kl = 2 * (lane & 3);
        float v00 = ws[kl][h],     v01 = ws[kl + 1][h];
        float v10 = ws[kl + 8][h], v11 = ws[kl + 9][h];
        // hi planes
        unsigned h00 = f16hi_bits(v00), h01 = f16hi_bits(v01);
        unsigned h10 = f16hi_bits(v10), h11 = f16hi_bits(v11);
        // lo planes (scaled)
        float l00 = (v00 - __half2float(__ushort_as_half((unsigned short)h00))) * LO_SCALE;
        float l01 = (v01 - __half2float(__ushort_as_half((unsigned short)h01))) * LO_SCALE;
        float l10 = (v10 - __half2float(__ushort_as_half((unsigned short)h10))) * LO_SCALE;
        float l11 = (v11 - __half2float(__ushort_as_half((unsigned short)h11))) * LO_SCALE;
        const int idx = (ksg * 16 + nf) * 32 + lane;
        g_Wpk[idx] = make_uint2(h00 | (h01 << 16), h10 | (h11 << 16));
        g_Wpk[PKSTRIDE + idx] = make_uint2(pkh(l00, l01), pkh(l10, l11));
    } else {
        // task router partials: block covers c-slice of 32 d
        const int c = bid - NKSG;            // 0..127
        const int b = t >> 7, h = t & 127;
        const float* tp = task + (size_t)b * D_ + c * 32;
        const float* w  = TW1 + (size_t)(c * 32) * H_ + h;
        float a0 = 0.f, a1 = 0.f, a2 = 0.f, a3 = 0.f;
#pragma unroll
        for (int d = 0; d < 32; d += 4) {
            a0 += tp[d + 0] * w[(size_t)(d + 0) * H_];
            a1 += tp[d + 1] * w[(size_t)(d + 1) * H_];
            a2 += tp[d + 2] * w[(size_t)(d + 2) * H_];
            a3 += tp[d + 3] * w[(size_t)(d + 3) * H_];
        }
        g_hpart[b][c][h] = (a0 + a1) + (a2 + a3);
    }
}

__global__ void task_finish_kernel(const float* __restrict__ Tb1,
                                   const float* __restrict__ TW2,
                                   const float* __restrict__ Tb2,
                                   const float* __restrict__ alpha) {
    __shared__ float hsm[B_][H_];
    __shared__ float lsm[B_][E_];
    int t = threadIdx.x;
#pragma unroll
    for (int b = 0; b < B_; b++) {
        float acc = Tb1[t];
        for (int c = 0; c < 128; c++) acc += g_hpart[b][c][t];
        hsm[b][t] = fmaxf(acc, 0.f);
    }
    __syncthreads();
    if (t < B_ * E_) {
        int b = t / E_, e = t % E_;
        float acc = Tb2[e];
#pragma unroll 8
        for (int j = 0; j < H_; j++) acc += hsm[b][j] * TW2[j * E_ + e];
        lsm[b][e] = acc;
    }
    __syncthreads();
    if (t < B_) {
        float mx = lsm[t][0];
#pragma unroll
        for (int e = 1; e < E_; e++) mx = fmaxf(mx, lsm[t][e]);
        float ex[E_], s = 0.f;
#pragma unroll
        for (int e = 0; e < E_; e++) { ex[e] = expf(lsm[t][e] - mx); s += ex[e]; }
        float inv = 1.f / s;
#pragma unroll
        for (int e = 0; e < E_; e++) g_task_w[t][e] = ex[e] * inv;
    }
    if (t == 0) g_alpha = 1.f / (1.f + expf(-alpha[0]));
}

// ---------------- main kernel: fp16-split HMMA GEMM + fused router ----------------
// 8 warps as 2(m) x 4(n), warp tile 32x32; A through SMEM, B fragments via direct LDG
extern __shared__ char sm[];

__global__ __launch_bounds__(NTH, 2)
void gemm_router_kernel(const float* __restrict__ X,
                        const float* __restrict__ b1,
                        const float* __restrict__ W2,
                        const float* __restrict__ b2,
                        float* __restrict__ out) {
    const unsigned sbase = s2u(sm);
    const int tid  = threadIdx.x;
    const int lane = tid & 31;
    const int wid  = tid >> 5;
    const int wm = wid >> 2, wn = wid & 3;          // 2(m) x 4(n)
    const int m_warp = wm * 32, n_warp = wn * 32;
    const int m0 = blockIdx.x * MTILE;

    float* W2s = (float*)(sm + OFF_W2);
    float* b1s = (float*)(sm + OFF_B1);
    float* b2s = (float*)(sm + OFF_B2);
    for (int i = tid; i < H_ * E_; i += NTH) W2s[i] = W2[i];
    if (tid < H_) b1s[tid] = b1[tid];
    if (tid < E_) b2s[tid] = b2[tid];

    // A ldmatrix addressing (XOR swizzle: chunk16 ^= row&7)
    const unsigned sxor = lane & 7;
    const unsigned c0A = lane >> 4;            // 0/1
    unsigned aRow[2];
#pragma unroll
    for (int mt = 0; mt < 2; mt++)
        aRow[mt] = (unsigned)((m_warp + mt * 16 + (lane & 15)) * 128);

    // B fragment base: fragments for this warp live at nf = wn*4 + nt
    const uint2* bBase = g_Wpk + (size_t)(wn * 4) * 32 + lane;

    float ch[2][4][4], cl[2][4][4];
#pragma unroll
    for (int mt = 0; mt < 2; mt++)
#pragma unroll
        for (int nt = 0; nt < 4; nt++)
#pragma unroll
            for (int q = 0; q < 4; q++) { ch[mt][nt][q] = 0.f; cl[mt][nt][q] = 0.f; }

    float4 xr[2];

    // X loader: half h (32 floats of K) of chunk ck
    auto load_x = [&](int ck, int h) {
        const int k0 = ck * KT + h * 32;
#pragma unroll
        for (int l = 0; l < 2; l++) {
            int idx = tid + NTH * l;
            int row = idx >> 3, kq = idx & 7;
            xr[l] = *(const float4*)(X + (size_t)(m0 + row) * D_ + k0 + kq * 4);
        }
    };
    auto store_x = [&](int buf, int h) {
        char* st = sm + buf * STAGE;
#pragma unroll
        for (int l = 0; l < 2; l++) {
            int idx = tid + NTH * l;
            int row = idx >> 3, kq = idx & 7;
            float4 x = xr[l];
            __half h0 = __float2half_rn(x.x), h1 = __float2half_rn(x.y);
            __half h2 = __float2half_rn(x.z), h3 = __float2half_rn(x.w);
            float l0 = (x.x - __half2float(h0)) * LO_SCALE;
            float l1 = (x.y - __half2float(h1)) * LO_SCALE;
            float l2 = (x.z - __half2float(h2)) * LO_SCALE;
            float l3 = (x.w - __half2float(h3)) * LO_SCALE;
            unsigned hi01 = (unsigned)__half_as_ushort(h0) | ((unsigned)__half_as_ushort(h1) << 16);
            unsigned hi23 = (unsigned)__half_as_ushort(h2) | ((unsigned)__half_as_ushort(h3) << 16);
            unsigned cc = (unsigned)((h * 4 + (kq >> 1)) ^ (row & 7));
            unsigned off = (unsigned)(row * 128) + cc * 16 + (kq & 1) * 8;
            *(uint2*)(st + OFF_AH + off) = make_uint2(hi01, hi23);
            *(uint2*)(st + OFF_AL + off) = make_uint2(pkh(l0, l1), pkh(l2, l3));
        }
    };

    auto mma_step = [&](unsigned bufoff, int ck, int ks) {
        // B fragments: one coalesced LDG.64 per fragment
        const uint2* bp = bBase + (size_t)(ck * 4 + ks) * (16 * 32);
        uint2 fh[4], fl[4];
#pragma unroll
        for (int nt = 0; nt < 4; nt++) {
            fh[nt] = bp[nt * 32];
            fl[nt] = bp[nt * 32 + PKSTRIDE];
        }
        // A fragments from SMEM
        unsigned cA = ((c0A + 2 * ks) ^ sxor) * 16;
        unsigned af[2][2][4];
#pragma unroll
        for (int mt = 0; mt < 2; mt++) {
            ldmx4(af[mt][0], sbase + bufoff + OFF_AH + aRow[mt] + cA);
            ldmx4(af[mt][1], sbase + bufoff + OFF_AL + aRow[mt] + cA);
        }
#pragma unroll
        for (int mt = 0; mt < 2; mt++)
#pragma unroll
            for (int nt = 0; nt < 4; nt++) {
                const unsigned* bh = reinterpret_cast<const unsigned*>(&fh[nt]);
                const unsigned* bl = reinterpret_cast<const unsigned*>(&fl[nt]);
                mma16816(ch[mt][nt], af[mt][0], bh);  // hi*hi
                mma16816(cl[mt][nt], af[mt][0], bl);  // hi*lo'
                mma16816(cl[mt][nt], af[mt][1], bh);  // lo'*hi
            }
    };

    // prologue: chunk 0 into buf 0
    load_x(0, 0);
    store_x(0, 0);
    load_x(0, 1);
    store_x(0, 1);

    for (int ck = 0; ck < NCHUNK; ck++) {
        const int buf = ck & 1;
        const unsigned bufoff = buf * STAGE;
        const bool more = (ck + 1 < NCHUNK);
        __syncthreads();
        if (more) load_x(ck + 1, 0);
        mma_step(bufoff, ck, 0);
        mma_step(bufoff, ck, 1);
        if (more) {
            store_x(buf ^ 1, 0);
            load_x(ck + 1, 1);
        }
        mma_step(bufoff, ck, 2);
        mma_step(bufoff, ck, 3);
        if (more) store_x(buf ^ 1, 1);
    }

    // ---- epilogue: h = relu(C + b1) -> smem ----
    __syncthreads();
    float* Hs = (float*)sm;               // [64][132]
#pragma unroll
    for (int mt = 0; mt < 2; mt++)
#pragma unroll
        for (int nt = 0; nt < 4; nt++) {
            int r0 = m_warp + mt * 16 + (lane >> 2);
            int c0 = n_warp + nt * 8 + 2 * (lane & 3);
            float bb0 = b1s[c0], bb1 = b1s[c0 + 1];
            float v00 = ch[mt][nt][0] + cl[mt][nt][0] * LO_INV + bb0;
            float v01 = ch[mt][nt][1] + cl[mt][nt][1] * LO_INV + bb1;
            float v10 = ch[mt][nt][2] + cl[mt][nt][2] * LO_INV + bb0;
            float v11 = ch[mt][nt][3] + cl[mt][nt][3] * LO_INV + bb1;
            *(float2*)(Hs + r0 * 132 + c0)       = make_float2(fmaxf(v00, 0.f), fmaxf(v01, 0.f));
            *(float2*)(Hs + (r0 + 8) * 132 + c0) = make_float2(fmaxf(v10, 0.f), fmaxf(v11, 0.f));
        }
    __syncthreads();

    // ---- per-row routing (64 threads, one row each) ----
    if (tid < MTILE) {
        float pl[E_];
#pragma unroll
        for (int e = 0; e < E_; e++) pl[e] = 0.f;
        const float4* hv4 = (const float4*)(Hs + tid * 132);
#pragma unroll 8
        for (int j = 0; j < 32; j++) {
            float4 hv = hv4[j];
            int col = j * 4;
#pragma unroll
            for (int e = 0; e < E_; e++) {
                pl[e] += hv.x * W2s[(col + 0) * E_ + e];
                pl[e] += hv.y * W2s[(col + 1) * E_ + e];
                pl[e] += hv.z * W2s[(col + 2) * E_ + e];
                pl[e] += hv.w * W2s[(col + 3) * E_ + e];
            }
        }

        const int row = m0 + tid;
        const int bidx = row >> 12;
        const float a = g_alpha, oma = 1.f - a;
        float l[E_], mx = -3.4e38f;
#pragma unroll
        for (int e = 0; e < E_; e++) {
            l[e] = pl[e] + b2s[e];
            mx = fmaxf(mx, l[e]);
        }
        float r[E_], s = 0.f;
#pragma unroll
        for (int e = 0; e < E_; e++) { r[e] = expf(l[e] - mx); s += r[e]; }
        float inv = 1.f / s;
#pragma unroll
        for (int e = 0; e < E_; e++) r[e] = oma * r[e] * inv + a * g_task_w[bidx][e];

        int i1 = 0; float v1 = r[0];
#pragma unroll
        for (int e = 1; e < E_; e++) if (r[e] > v1) { v1 = r[e]; i1 = e; }
        int i2 = (i1 == 0) ? 1 : 0; float v2 = r[i2];
#pragma unroll
        for (int e = 0; e < E_; e++)
            if (e != i1 && e != i2 && r[e] > v2) { v2 = r[e]; i2 = e; }

        float e2  = expf(v2 - v1);
        float den = 1.f / (1.f + e2);
        float o[E_];
#pragma unroll
        for (int e = 0; e < E_; e++) o[e] = 0.f;
        o[i1] = den;
        o[i2] = e2 * den;
        float4* op = (float4*)(out + (size_t)row * E_);
        op[0] = make_float4(o[0], o[1], o[2], o[3]);
        op[1] = make_float4(o[4], o[5], o[6], o[7]);
    }
}

// ---------------- launch ----------------
extern "C" void kernel_launch(void* const* d_in, const int* in_sizes, int n_in,
                              void* d_out, int out_size) {
    const float* X     = (const float*)d_in[0];
    const float* task  = (const float*)d_in[1];
    const float* W1    = (const float*)d_in[2];
    const float* b1    = (const float*)d_in[3];
    const float* W2    = (const float*)d_in[4];
    const float* b2    = (const float*)d_in[5];
    const float* TW1   = (const float*)d_in[6];
    const float* Tb1   = (const float*)d_in[7];
    const float* TW2   = (const float*)d_in[8];
    const float* Tb2   = (const float*)d_in[9];
    const float* alpha = (const float*)d_in[10];
    float* out = (float*)d_out;

    cudaFuncSetAttribute(gemm_router_kernel,
                         cudaFuncAttributeMaxDynamicSharedMemorySize, SMEM_BYTES);

    prelude_kernel<<<NKSG + 128, 512>>>(W1, task, TW1);
    task_finish_kernel<<<1, 128>>>(Tb1, TW2, Tb2, alpha);
    gemm_router_kernel<<<M_ / MTILE, NTH, SMEM_BYTES>>>(X, b1, W2, b2, out);
}

// round 16
// speedup vs baseline: 1.1119x; 1.1119x over previous
#include <cuda_runtime.h>
#include <cuda_fp16.h>
#include <math.h>
#include <stdint.h>

#define B_ 4
#define S_ 4096
#define D_ 4096
#define H_ 128
#define E_ 8
#define M_ (B_*S_)

#define MTILE 64
#define KT 64
#define NCHUNK (D_/KT)        // 64
#define NTH 256
// XOR-swizzled planes: 128B rows, chunk16 ^= (row & 7)
#define APL 8192              // 64 rows * 128B
#define BPL 16384             // 128 rows * 128B
#define OFF_AH 0
#define OFF_AL APL
#define OFF_BH (2*APL)
#define OFF_BL (2*APL + BPL)
#define STAGE (2*APL + 2*BPL) // 49152
#define OFF_W2 (2*STAGE)      // 98304
#define OFF_B1 (OFF_W2 + H_*E_*4)
#define OFF_B2 (OFF_B1 + H_*4)
#define SMEM_BYTES (OFF_B2 + 64)

#define LO_SCALE 2048.0f
#define LO_INV   (1.0f/2048.0f)

// ---------------- device globals ----------------
__device__ __align__(16) unsigned short g_W[2][H_ * D_]; // W1^T planes [hi, lo*2048][h*D+k]
__device__ float g_hpart[B_][32][H_];
__device__ float g_task_w[B_][E_];
__device__ float g_alpha;

// ---------------- helpers ----------------
__device__ __forceinline__ unsigned s2u(const void* p) {
    unsigned r;
    asm("{ .reg .u64 t; cvta.to.shared.u64 t, %1; cvt.u32.u64 %0, t; }" : "=r"(r) : "l"(p));
    return r;
}
__device__ __forceinline__ unsigned pkh(float lo, float hi) { // f16x2 {lo, hi}
    unsigned r;
    asm("cvt.rn.f16x2.f32 %0, %1, %2;" : "=r"(r) : "f"(hi), "f"(lo));
    return r;
}
__device__ __forceinline__ void ldmx4(unsigned* r, unsigned a) {
    asm volatile("ldmatrix.sync.aligned.m8n8.x4.shared.b16 {%0,%1,%2,%3}, [%4];"
                 : "=r"(r[0]), "=r"(r[1]), "=r"(r[2]), "=r"(r[3]) : "r"(a));
}
__device__ __forceinline__ void mma16816(float* c, const unsigned* a, const unsigned* b) {
    asm volatile(
        "mma.sync.aligned.m16n8k16.row.col.f32.f16.f16.f32 "
        "{%0,%1,%2,%3}, {%4,%5,%6,%7}, {%8,%9}, {%0,%1,%2,%3};"
        : "+f"(c[0]), "+f"(c[1]), "+f"(c[2]), "+f"(c[3])
        : "r"(a[0]), "r"(a[1]), "r"(a[2]), "r"(a[3]), "r"(b[0]), "r"(b[1]));
}
__device__ __forceinline__ void cp16(unsigned dst, const void* src) {
    asm volatile("cp.async.cg.shared.global [%0], [%1], 16;" :: "r"(dst), "l"(src) : "memory");
}
__device__ __forceinline__ void cp_commit() {
    asm volatile("cp.async.commit_group;" ::: "memory");
}
__device__ __forceinline__ void cp_wait0() {
    asm volatile("cp.async.wait_group 0;" ::: "memory");
}

// ---------------- prelude: W1 transpose + fp16 split (lo scaled by 2048) ----------------
__global__ void split_w1_kernel(const float* __restrict__ W1) {
    __shared__ float ts[32][33];
    int k0 = blockIdx.x * 32, h0 = blockIdx.y * 32;
    int tx = threadIdx.x, ty = threadIdx.y;
    ts[ty][tx] = W1[(size_t)(k0 + ty) * H_ + h0 + tx];
    __syncthreads();
    float v = ts[tx][ty];                 // (k=k0+tx, h=h0+ty)
    __half hv = __float2half_rn(v);
    float lo = (v - __half2float(hv)) * LO_SCALE;
    __half lv = __float2half_rn(lo);
    size_t idx = (size_t)(h0 + ty) * D_ + k0 + tx;
    g_W[0][idx] = __half_as_ushort(hv);
    g_W[1][idx] = __half_as_ushort(lv);
}

// ---------------- task router ----------------
__global__ void task_partial_kernel(const float* __restrict__ task,
                                    const float* __restrict__ TW1) {
    int c = blockIdx.x, b = blockIdx.y, t = threadIdx.x;
    const float* tp = task + (size_t)b * D_ + c * 128;
    const float* w  = TW1 + (size_t)(c * 128) * H_ + t;
    float acc = 0.f;
#pragma unroll 8
    for (int d = 0; d < 128; d++)
        acc += tp[d] * w[(size_t)d * H_];
    g_hpart[b][c][t] = acc;
}

__global__ void task_finish_kernel(const float* __restrict__ Tb1,
                                   const float* __restrict__ TW2,
                                   const float* __restrict__ Tb2,
                                   const float* __restrict__ alpha) {
    __shared__ float hsm[B_][H_];
    __shared__ float lsm[B_][E_];
    int t = threadIdx.x;
#pragma unroll
    for (int b = 0; b < B_; b++) {
        float acc = Tb1[t];
#pragma unroll
        for (int c = 0; c < 32; c++) acc += g_hpart[b][c][t];
        hsm[b][t] = fmaxf(acc, 0.f);
    }
    __syncthreads();
    if (t < B_ * E_) {
        int b = t / E_, e = t % E_;
        float acc = Tb2[e];
#pragma unroll 8
        for (int j = 0; j < H_; j++) acc += hsm[b][j] * TW2[j * E_ + e];
        lsm[b][e] = acc;
    }
    __syncthreads();
    if (t < B_) {
        float mx = lsm[t][0];
#pragma unroll
        for (int e = 1; e < E_; e++) mx = fmaxf(mx, lsm[t][e]);
        float ex[E_], s = 0.f;
#pragma unroll
        for (int e = 0; e < E_; e++) { ex[e] = expf(lsm[t][e] - mx); s += ex[e]; }
        float inv = 1.f / s;
#pragma unroll
        for (int e = 0; e < E_; e++) g_task_w[t][e] = ex[e] * inv;
    }
    if (t == 0) g_alpha = 1.f / (1.f + expf(-alpha[0]));
}

// ---------------- main kernel: fp16-split HMMA GEMM + fused router ----------------
// 8 warps as 2(m) x 4(n), warp tile 32x32
extern __shared__ char sm[];

__global__ __launch_bounds__(NTH, 2)
void gemm_router_kernel(const float* __restrict__ X,
                        const float* __restrict__ b1,
                        const float* __restrict__ W2,
                        const float* __restrict__ b2,
                        float* __restrict__ out) {
    const unsigned sbase = s2u(sm);
    const int tid  = threadIdx.x;
    const int lane = tid & 31;
    const int wid  = tid >> 5;
    const int wm = wid >> 2, wn = wid & 3;          // 2(m) x 4(n)
    const int m_warp = wm * 32, n_warp = wn * 32;
    const int m0 = blockIdx.x * MTILE;

    float* W2s = (float*)(sm + OFF_W2);
    float* b1s = (float*)(sm + OFF_B1);
    float* b2s = (float*)(sm + OFF_B2);
    for (int i = tid; i < H_ * E_; i += NTH) W2s[i] = W2[i];
    if (tid < H_) b1s[tid] = b1[tid];
    if (tid < E_) b2s[tid] = b2[tid];

    // ldmatrix addressing (XOR swizzle: chunk16 ^= row&7)
    const unsigned sxor = lane & 7;
    const unsigned c0A = lane >> 4;            // 0/1
    const unsigned c0B = (lane >> 3) & 1;      // 0/1
    unsigned aRow[2], bRow[2];
#pragma unroll
    for (int mt = 0; mt < 2; mt++)
        aRow[mt] = (unsigned)((m_warp + mt * 16 + (lane & 15)) * 128);
#pragma unroll
    for (int np = 0; np < 2; np++)
        bRow[np] = (unsigned)((n_warp + np * 16 + ((lane >> 4) << 3) + (lane & 7)) * 128);

    float ch[2][4][4], cl[2][4][4];
#pragma unroll
    for (int mt = 0; mt < 2; mt++)
#pragma unroll
        for (int nt = 0; nt < 4; nt++)
#pragma unroll
            for (int q = 0; q < 4; q++) { ch[mt][nt][q] = 0.f; cl[mt][nt][q] = 0.f; }

    float4 xr[2];

    // X loader: half h (32 floats of K) of chunk ck
    auto load_x = [&](int ck, int h) {
        const int k0 = ck * KT + h * 32;
#pragma unroll
        for (int l = 0; l < 2; l++) {
            int idx = tid + NTH * l;
            int row = idx >> 3, kq = idx & 7;
            xr[l] = *(const float4*)(X + (size_t)(m0 + row) * D_ + k0 + kq * 4);
        }
    };
    auto store_x = [&](int buf, int h) {
        char* st = sm + buf * STAGE;
#pragma unroll
        for (int l = 0; l < 2; l++) {
            int idx = tid + NTH * l;
            int row = idx >> 3, kq = idx & 7;
            float4 x = xr[l];
            __half h0 = __float2half_rn(x.x), h1 = __float2half_rn(x.y);
            __half h2 = __float2half_rn(x.z), h3 = __float2half_rn(x.w);
            float l0 = (x.x - __half2float(h0)) * LO_SCALE;
            float l1 = (x.y - __half2float(h1)) * LO_SCALE;
            float l2 = (x.z - __half2float(h2)) * LO_SCALE;
            float l3 = (x.w - __half2float(h3)) * LO_SCALE;
            unsigned hi01 = (unsigned)__half_as_ushort(h0) | ((unsigned)__half_as_ushort(h1) << 16);
            unsigned hi23 = (unsigned)__half_as_ushort(h2) | ((unsigned)__half_as_ushort(h3) << 16);
            unsigned cc = (unsigned)((h * 4 + (kq >> 1)) ^ (row & 7));
            unsigned off = (unsigned)(row * 128) + cc * 16 + (kq & 1) * 8;
            *(uint2*)(st + OFF_AH + off) = make_uint2(hi01, hi23);
            *(uint2*)(st + OFF_AL + off) = make_uint2(pkh(l0, l1), pkh(l2, l3));
        }
    };
    auto cp_b = [&](int ck, int buf) {
        const int k0 = ck * KT;
        const unsigned bo = sbase + buf * STAGE;
#pragma unroll
        for (int l = 0; l < 4; l++) {
            int idx = tid + NTH * l;              // 0..1023
            int row = idx >> 3, cc = idx & 7;
            unsigned sw = (unsigned)((cc ^ (row & 7)) * 16) + (unsigned)(row * 128);
            const size_t src = (size_t)row * D_ + k0 + cc * 8;
            cp16(bo + OFF_BH + sw, &g_W[0][src]);
            cp16(bo + OFF_BL + sw, &g_W[1][src]);
        }
    };

    auto mma_step = [&](unsigned bufoff, int ks) {
        unsigned cA = ((c0A + 2 * ks) ^ sxor) * 16;
        unsigned cB = ((c0B + 2 * ks) ^ sxor) * 16;
        unsigned af[2][2][4];
#pragma unroll
        for (int mt = 0; mt < 2; mt++) {
            ldmx4(af[mt][0], sbase + bufoff + OFF_AH + aRow[mt] + cA);
            ldmx4(af[mt][1], sbase + bufoff + OFF_AL + aRow[mt] + cA);
        }
        unsigned bf[2][2][4];
#pragma unroll
        for (int np = 0; np < 2; np++) {
            ldmx4(bf[np][0], sbase + bufoff + OFF_BH + bRow[np] + cB);
            ldmx4(bf[np][1], sbase + bufoff + OFF_BL + bRow[np] + cB);
        }
#pragma unroll
        for (int mt = 0; mt < 2; mt++)
#pragma unroll
            for (int nt = 0; nt < 4; nt++) {
                const unsigned* bh = &bf[nt >> 1][0][(nt & 1) * 2];
                const unsigned* bl = &bf[nt >> 1][1][(nt & 1) * 2];
                mma16816(ch[mt][nt], af[mt][0], bh);  // hi*hi
                mma16816(cl[mt][nt], af[mt][0], bl);  // hi*lo'
                mma16816(cl[mt][nt], af[mt][1], bh);  // lo'*hi
            }
    };

    // prologue: chunk 0 into buf 0
    load_x(0, 0);
    cp_b(0, 0);
    cp_commit();
    store_x(0, 0);
    load_x(0, 1);
    store_x(0, 1);

    for (int ck = 0; ck < NCHUNK; ck++) {
        const int buf = ck & 1;
        const unsigned bufoff = buf * STAGE;
        const bool more = (ck + 1 < NCHUNK);
        cp_wait0();
        __syncthreads();
        if (more) {
            load_x(ck + 1, 0);
            cp_b(ck + 1, buf ^ 1);
            cp_commit();
        }
        mma_step(bufoff, 0);
        mma_step(bufoff, 1);
        if (more) {
            store_x(buf ^ 1, 0);
            load_x(ck + 1, 1);
        }
        mma_step(bufoff, 2);
        mma_step(bufoff, 3);
        if (more) store_x(buf ^ 1, 1);
    }

    // ---- epilogue: h = relu(C + b1) -> smem ----
    __syncthreads();
    float* Hs = (float*)sm;               // [64][132]
#pragma unroll
    for (int mt = 0; mt < 2; mt++)
#pragma unroll
        for (int nt = 0; nt < 4; nt++) {
            int r0 = m_warp + mt * 16 + (lane >> 2);
            int c0 = n_warp + nt * 8 + 2 * (lane & 3);
            float bb0 = b1s[c0], bb1 = b1s[c0 + 1];
            float v00 = ch[mt][nt][0] + cl[mt][nt][0] * LO_INV + bb0;
            float v01 = ch[mt][nt][1] + cl[mt][nt][1] * LO_INV + bb1;
            float v10 = ch[mt][nt][2] + cl[mt][nt][2] * LO_INV + bb0;
            float v11 = ch[mt][nt][3] + cl[mt][nt][3] * LO_INV + bb1;
            *(float2*)(Hs + r0 * 132 + c0)       = make_float2(fmaxf(v00, 0.f), fmaxf(v01, 0.f));
            *(float2*)(Hs + (r0 + 8) * 132 + c0) = make_float2(fmaxf(v10, 0.f), fmaxf(v11, 0.f));
        }
    __syncthreads();

    // ---- per-row routing (64 threads, one row each) ----
    if (tid < MTILE) {
        float pl[E_];
#pragma unroll
        for (int e = 0; e < E_; e++) pl[e] = 0.f;
        const float4* hv4 = (const float4*)(Hs + tid * 132);
#pragma unroll 8
        for (int j = 0; j < 32; j++) {
            float4 hv = hv4[j];
            int col = j * 4;
#pragma unroll
            for (int e = 0; e < E_; e++) {
                pl[e] += hv.x * W2s[(col + 0) * E_ + e];
                pl[e] += hv.y * W2s[(col + 1) * E_ + e];
                pl[e] += hv.z * W2s[(col + 2) * E_ + e];
                pl[e] += hv.w * W2s[(col + 3) * E_ + e];
            }
        }

        const int row = m0 + tid;
        const int bidx = row >> 12;
        const float a = g_alpha, oma = 1.f - a;
        float l[E_], mx = -3.4e38f;
#pragma unroll
        for (int e = 0; e < E_; e++) {
            l[e] = pl[e] + b2s[e];
            mx = fmaxf(mx, l[e]);
        }
        float r[E_], s = 0.f;
#pragma unroll
        for (int e = 0; e < E_; e++) { r[e] = expf(l[e] - mx); s += r[e]; }
        float inv = 1.f / s;
#pragma unroll
        for (int e = 0; e < E_; e++) r[e] = oma * r[e] * inv + a * g_task_w[bidx][e];

        int i1 = 0; float v1 = r[0];
#pragma unroll
        for (int e = 1; e < E_; e++) if (r[e] > v1) { v1 = r[e]; i1 = e; }
        int i2 = (i1 == 0) ? 1 : 0; float v2 = r[i2];
#pragma unroll
        for (int e = 0; e < E_; e++)
            if (e != i1 && e != i2 && r[e] > v2) { v2 = r[e]; i2 = e; }

        float e2  = expf(v2 - v1);
        float den = 1.f / (1.f + e2);
        float o[E_];
#pragma unroll
        for (int e = 0; e < E_; e++) o[e] = 0.f;
        o[i1] = den;
        o[i2] = e2 * den;
        float4* op = (float4*)(out + (size_t)row * E_);
        op[0] = make_float4(o[0], o[1], o[2], o[3]);
        op[1] = make_float4(o[4], o[5], o[6], o[7]);
    }
}

// ---------------- launch ----------------
extern "C" void kernel_launch(void* const* d_in, const int* in_sizes, int n_in,
                              void* d_out, int out_size) {
    const float* X     = (const float*)d_in[0];
    const float* task  = (const float*)d_in[1];
    const float* W1    = (const float*)d_in[2];
    const float* b1    = (const float*)d_in[3];
    const float* W2    = (const float*)d_in[4];
    const float* b2    = (const float*)d_in[5];
    const float* TW1   = (const float*)d_in[6];
    const float* Tb1   = (const float*)d_in[7];
    const float* TW2   = (const float*)d_in[8];
    const float* Tb2   = (const float*)d_in[9];
    const float* alpha = (const float*)d_in[10];
    float* out = (float*)d_out;

    cudaFuncSetAttribute(gemm_router_kernel,
                         cudaFuncAttributeMaxDynamicSharedMemorySize, SMEM_BYTES);

    split_w1_kernel<<<dim3(D_ / 32, H_ / 32), dim3(32, 32)>>>(W1);
    task_partial_kernel<<<dim3(32, B_), 128>>>(task, TW1);
    task_finish_kernel<<<1, 128>>>(Tb1, TW2, Tb2, alpha);
    gemm_router_kernel<<<M_ / MTILE, NTH, SMEM_BYTES>>>(X, b1, W2, b2, out);
}

// round 17
// speedup vs baseline: 1.1740x; 1.0558x over previous
#include <cuda_runtime.h>
#include <cuda_fp16.h>
#include <math.h>
#include <stdint.h>

#define B_ 4
#define S_ 4096
#define D_ 4096
#define H_ 128
#define E_ 8
#define M_ (B_*S_)

#define MTILE 64
#define KT 64
#define NCHUNK (D_/KT)        // 64
#define NTH 256
// XOR-swizzled planes: 128B rows, chunk16 ^= (row & 7)
#define APL 8192              // 64 rows * 128B
#define BPL 16384             // 128 rows * 128B
#define OFF_AH 0
#define OFF_AL APL
#define OFF_BH (2*APL)
#define OFF_BL (2*APL + BPL)
#define STAGE (2*APL + 2*BPL) // 49152
#define OFF_W2 (2*STAGE)      // 98304
#define OFF_B1 (OFF_W2 + H_*E_*4)
#define OFF_B2 (OFF_B1 + H_*4)
#define SMEM_BYTES (OFF_B2 + 64)

#define LO_SCALE 2048.0f
#define LO_INV   (1.0f/2048.0f)

// ---------------- device globals ----------------
__device__ __align__(16) unsigned short g_W[2][H_ * D_]; // W1^T planes [hi, lo*2048][h*D+k]
__device__ float g_hpart[B_][128][H_];
__device__ float g_task_w[B_][E_];
__device__ float g_alpha;
__device__ int   g_cnt;          // task-block completion counter (reset by finisher)

// ---------------- helpers ----------------
__device__ __forceinline__ unsigned s2u(const void* p) {
    unsigned r;
    asm("{ .reg .u64 t; cvta.to.shared.u64 t, %1; cvt.u32.u64 %0, t; }" : "=r"(r) : "l"(p));
    return r;
}
__device__ __forceinline__ unsigned pkh(float lo, float hi) { // f16x2 {lo, hi}
    unsigned r;
    asm("cvt.rn.f16x2.f32 %0, %1, %2;" : "=r"(r) : "f"(hi), "f"(lo));
    return r;
}
__device__ __forceinline__ void ldmx4(unsigned* r, unsigned a) {
    asm volatile("ldmatrix.sync.aligned.m8n8.x4.shared.b16 {%0,%1,%2,%3}, [%4];"
                 : "=r"(r[0]), "=r"(r[1]), "=r"(r[2]), "=r"(r[3]) : "r"(a));
}
__device__ __forceinline__ void mma16816(float* c, const unsigned* a, const unsigned* b) {
    asm volatile(
        "mma.sync.aligned.m16n8k16.row.col.f32.f16.f16.f32 "
        "{%0,%1,%2,%3}, {%4,%5,%6,%7}, {%8,%9}, {%0,%1,%2,%3};"
        : "+f"(c[0]), "+f"(c[1]), "+f"(c[2]), "+f"(c[3])
        : "r"(a[0]), "r"(a[1]), "r"(a[2]), "r"(a[3]), "r"(b[0]), "r"(b[1]));
}
__device__ __forceinline__ void cp16(unsigned dst, const void* src) {
    asm volatile("cp.async.cg.shared.global [%0], [%1], 16;" :: "r"(dst), "l"(src) : "memory");
}
__device__ __forceinline__ void cp_commit() {
    asm volatile("cp.async.commit_group;" ::: "memory");
}
__device__ __forceinline__ void cp_wait0() {
    asm volatile("cp.async.wait_group 0;" ::: "memory");
}

// ---------------- single prelude: W1 split + task partials + last-block finish ----------------
__global__ void prelude_kernel(const float* __restrict__ W1,
                               const float* __restrict__ task,
                               const float* __restrict__ TW1,
                               const float* __restrict__ Tb1,
                               const float* __restrict__ TW2,
                               const float* __restrict__ Tb2,
                               const float* __restrict__ alpha) {
    const int bid = blockIdx.x;
    const int t = threadIdx.x;
    if (bid < 512) {
        // W1 transpose + fp16 split (lo scaled by 2048)
        __shared__ float ts[32][33];
        int k0 = (bid & 127) * 32, h0 = (bid >> 7) * 32;
        int tx = t & 31, ty = t >> 5;
        ts[ty][tx] = W1[(size_t)(k0 + ty) * H_ + h0 + tx];
        __syncthreads();
        float v = ts[tx][ty];                 // (k=k0+tx, h=h0+ty)
        __half hv = __float2half_rn(v);
        float lo = (v - __half2float(hv)) * LO_SCALE;
        __half lv = __float2half_rn(lo);
        size_t idx = (size_t)(h0 + ty) * D_ + k0 + tx;
        g_W[0][idx] = __half_as_ushort(hv);
        g_W[1][idx] = __half_as_ushort(lv);
        return;
    }

    // ---- task router partial: block covers c-slice of 32 d ----
    __shared__ float hsm[B_][H_];
    __shared__ float lsm[B_][E_];
    __shared__ int sflag;
    if (t < 512) {
        int c = bid - 512;            // 0..127
        int b = t >> 7, h = t & 127;
        const float* tp = task + (size_t)b * D_ + c * 32;
        const float* w  = TW1 + (size_t)(c * 32) * H_ + h;
        float a0 = 0.f, a1 = 0.f, a2 = 0.f, a3 = 0.f;
#pragma unroll
        for (int d = 0; d < 32; d += 4) {
            a0 += tp[d + 0] * w[(size_t)(d + 0) * H_];
            a1 += tp[d + 1] * w[(size_t)(d + 1) * H_];
            a2 += tp[d + 2] * w[(size_t)(d + 2) * H_];
            a3 += tp[d + 3] * w[(size_t)(d + 3) * H_];
        }
        g_hpart[b][c][h] = (a0 + a1) + (a2 + a3);
    }
    __syncthreads();
    __threadfence();
    if (t == 0) {
        int old = atomicAdd(&g_cnt, 1);
        sflag = (old == 127);
    }
    __syncthreads();
    if (!sflag) return;

    // ---- last task block performs the finish ----
    __threadfence();   // acquire all partial writes
    if (t < 512) {
        int b = t >> 7, h = t & 127;
        float acc = Tb1[h];
        for (int c = 0; c < 128; c++) acc += g_hpart[b][c][h];
        hsm[b][h] = fmaxf(acc, 0.f);
    }
    __syncthreads();
    if (t < B_ * E_) {
        int b = t / E_, e = t % E_;
        float acc = Tb2[e];
#pragma unroll 8
        for (int j = 0; j < H_; j++) acc += hsm[b][j] * TW2[j * E_ + e];
        lsm[b][e] = acc;
    }
    __syncthreads();
    if (t < B_) {
        float mx = lsm[t][0];
#pragma unroll
        for (int e = 1; e < E_; e++) mx = fmaxf(mx, lsm[t][e]);
        float ex[E_], s = 0.f;
#pragma unroll
        for (int e = 0; e < E_; e++) { ex[e] = expf(lsm[t][e] - mx); s += ex[e]; }
        float inv = 1.f / s;
#pragma unroll
        for (int e = 0; e < E_; e++) g_task_w[t][e] = ex[e] * inv;
    }
    if (t == 0) {
        g_alpha = 1.f / (1.f + expf(-alpha[0]));
        g_cnt = 0;                       // reset for next graph replay
    }
}

// ---------------- main kernel: fp16-split HMMA GEMM + fused router ----------------
// 8 warps as 2(m) x 4(n), warp tile 32x32  (byte-identical to the measured-best R8/R16 mainloop)
extern __shared__ char sm[];

__global__ __launch_bounds__(NTH, 2)
void gemm_router_kernel(const float* __restrict__ X,
                        const float* __restrict__ b1,
                        const float* __restrict__ W2,
                        const float* __restrict__ b2,
                        float* __restrict__ out) {
    const unsigned sbase = s2u(sm);
    const int tid  = threadIdx.x;
    const int lane = tid & 31;
    const int wid  = tid >> 5;
    const int wm = wid >> 2, wn = wid & 3;          // 2(m) x 4(n)
    const int m_warp = wm * 32, n_warp = wn * 32;
    const int m0 = blockIdx.x * MTILE;

    float* W2s = (float*)(sm + OFF_W2);
    float* b1s = (float*)(sm + OFF_B1);
    float* b2s = (float*)(sm + OFF_B2);
    for (int i = tid; i < H_ * E_; i += NTH) W2s[i] = W2[i];
    if (tid < H_) b1s[tid] = b1[tid];
    if (tid < E_) b2s[tid] = b2[tid];

    // ldmatrix addressing (XOR swizzle: chunk16 ^= row&7)
    const unsigned sxor = lane & 7;
    const unsigned c0A = lane >> 4;            // 0/1
    const unsigned c0B = (lane >> 3) & 1;      // 0/1
    unsigned aRow[2], bRow[2];
#pragma unroll
    for (int mt = 0; mt < 2; mt++)
        aRow[mt] = (unsigned)((m_warp + mt * 16 + (lane & 15)) * 128);
#pragma unroll
    for (int np = 0; np < 2; np++)
        bRow[np] = (unsigned)((n_warp + np * 16 + ((lane >> 4) << 3) + (lane & 7)) * 128);

    float ch[2][4][4], cl[2][4][4];
#pragma unroll
    for (int mt = 0; mt < 2; mt++)
#pragma unroll
        for (int nt = 0; nt < 4; nt++)
#pragma unroll
            for (int q = 0; q < 4; q++) { ch[mt][nt][q] = 0.f; cl[mt][nt][q] = 0.f; }

    float4 xr[2];

    // X loader: half h (32 floats of K) of chunk ck
    auto load_x = [&](int ck, int h) {
        const int k0 = ck * KT + h * 32;
#pragma unroll
        for (int l = 0; l < 2; l++) {
            int idx = tid + NTH * l;
            int row = idx >> 3, kq = idx & 7;
            xr[l] = *(const float4*)(X + (size_t)(m0 + row) * D_ + k0 + kq * 4);
        }
    };
    auto store_x = [&](int buf, int h) {
        char* st = sm + buf * STAGE;
#pragma unroll
        for (int l = 0; l < 2; l++) {
            int idx = tid + NTH * l;
            int row = idx >> 3, kq = idx & 7;
            float4 x = xr[l];
            __half h0 = __float2half_rn(x.x), h1 = __float2half_rn(x.y);
            __half h2 = __float2half_rn(x.z), h3 = __float2half_rn(x.w);
            float l0 = (x.x - __half2float(h0)) * LO_SCALE;
            float l1 = (x.y - __half2float(h1)) * LO_SCALE;
            float l2 = (x.z - __half2float(h2)) * LO_SCALE;
            float l3 = (x.w - __half2float(h3)) * LO_SCALE;
            unsigned hi01 = (unsigned)__half_as_ushort(h0) | ((unsigned)__half_as_ushort(h1) << 16);
            unsigned hi23 = (unsigned)__half_as_ushort(h2) | ((unsigned)__half_as_ushort(h3) << 16);
            unsigned cc = (unsigned)((h * 4 + (kq >> 1)) ^ (row & 7));
            unsigned off = (unsigned)(row * 128) + cc * 16 + (kq & 1) * 8;
            *(uint2*)(st + OFF_AH + off) = make_uint2(hi01, hi23);
            *(uint2*)(st + OFF_AL + off) = make_uint2(pkh(l0, l1), pkh(l2, l3));
        }
    };
    auto cp_b = [&](int ck, int buf) {
        const int k0 = ck * KT;
        const unsigned bo = sbase + buf * STAGE;
#pragma unroll
        for (int l = 0; l < 4; l++) {
            int idx = tid + NTH * l;              // 0..1023
            int row = idx >> 3, cc = idx & 7;
            unsigned sw = (unsigned)((cc ^ (row & 7)) * 16) + (unsigned)(row * 128);
            const size_t src = (size_t)row * D_ + k0 + cc * 8;
            cp16(bo + OFF_BH + sw, &g_W[0][src]);
            cp16(bo + OFF_BL + sw, &g_W[1][src]);
        }
    };

    auto mma_step = [&](unsigned bufoff, int ks) {
        unsigned cA = ((c0A + 2 * ks) ^ sxor) * 16;
        unsigned cB = ((c0B + 2 * ks) ^ sxor) * 16;
        unsigned af[2][2][4];
#pragma unroll
        for (int mt = 0; mt < 2; mt++) {
            ldmx4(af[mt][0], sbase + bufoff + OFF_AH + aRow[mt] + cA);
            ldmx4(af[mt][1], sbase + bufoff + OFF_AL + aRow[mt] + cA);
        }
        unsigned bf[2][2][4];
#pragma unroll
        for (int np = 0; np < 2; np++) {
            ldmx4(bf[np][0], sbase + bufoff + OFF_BH + bRow[np] + cB);
            ldmx4(bf[np][1], sbase + bufoff + OFF_BL + bRow[np] + cB);
        }
#pragma unroll
        for (int mt = 0; mt < 2; mt++)
#pragma unroll
            for (int nt = 0; nt < 4; nt++) {
                const unsigned* bh = &bf[nt >> 1][0][(nt & 1) * 2];
                const unsigned* bl = &bf[nt >> 1][1][(nt & 1) * 2];
                mma16816(ch[mt][nt], af[mt][0], bh);  // hi*hi
                mma16816(cl[mt][nt], af[mt][0], bl);  // hi*lo'
                mma16816(cl[mt][nt], af[mt][1], bh);  // lo'*hi
            }
    };

    // prologue: chunk 0 into buf 0
    load_x(0, 0);
    cp_b(0, 0);
    cp_commit();
    store_x(0, 0);
    load_x(0, 1);
    store_x(0, 1);

    for (int ck = 0; ck < NCHUNK; ck++) {
        const int buf = ck & 1;
        const unsigned bufoff = buf * STAGE;
        const bool more = (ck + 1 < NCHUNK);
        cp_wait0();
        __syncthreads();
        if (more) {
            load_x(ck + 1, 0);
            cp_b(ck + 1, buf ^ 1);
            cp_commit();
        }
        mma_step(bufoff, 0);
        mma_step(bufoff, 1);
        if (more) {
            store_x(buf ^ 1, 0);
            load_x(ck + 1, 1);
        }
        mma_step(bufoff, 2);
        mma_step(bufoff, 3);
        if (more) store_x(buf ^ 1, 1);
    }

    // ---- epilogue: h = relu(C + b1) -> smem ----
    __syncthreads();
    float* Hs = (float*)sm;               // [64][132]
#pragma unroll
    for (int mt = 0; mt < 2; mt++)
#pragma unroll
        for (int nt = 0; nt < 4; nt++) {
            int r0 = m_warp + mt * 16 + (lane >> 2);
            int c0 = n_warp + nt * 8 + 2 * (lane & 3);
            float bb0 = b1s[c0], bb1 = b1s[c0 + 1];
            float v00 = ch[mt][nt][0] + cl[mt][nt][0] * LO_INV + bb0;
            float v01 = ch[mt][nt][1] + cl[mt][nt][1] * LO_INV + bb1;
            float v10 = ch[mt][nt][2] + cl[mt][nt][2] * LO_INV + bb0;
            float v11 = ch[mt][nt][3] + cl[mt][nt][3] * LO_INV + bb1;
            *(float2*)(Hs + r0 * 132 + c0)       = make_float2(fmaxf(v00, 0.f), fmaxf(v01, 0.f));
            *(float2*)(Hs + (r0 + 8) * 132 + c0) = make_float2(fmaxf(v10, 0.f), fmaxf(v11, 0.f));
        }
    __syncthreads();

    // ---- per-row routing (64 threads, one row each) ----
    if (tid < MTILE) {
        float pl[E_];
#pragma unroll
        for (int e = 0; e < E_; e++) pl[e] = 0.f;
        const float4* hv4 = (const float4*)(Hs + tid * 132);
#pragma unroll 8
        for (int j = 0; j < 32; j++) {
            float4 hv = hv4[j];
            int col = j * 4;
#pragma unroll
            for (int e = 0; e < E_; e++) {
                pl[e] += hv.x * W2s[(col + 0) * E_ + e];
                pl[e] += hv.y * W2s[(col + 1) * E_ + e];
                pl[e] += hv.z * W2s[(col + 2) * E_ + e];
                pl[e] += hv.w * W2s[(col + 3) * E_ + e];
            }
        }

        const int row = m0 + tid;
        const int bidx = row >> 12;
        const float a = g_alpha, oma = 1.f - a;
        float l[E_], mx = -3.4e38f;
#pragma unroll
        for (int e = 0; e < E_; e++) {
            l[e] = pl[e] + b2s[e];
            mx = fmaxf(mx, l[e]);
        }
        float r[E_], s = 0.f;
#pragma unroll
        for (int e = 0; e < E_; e++) { r[e] = expf(l[e] - mx); s += r[e]; }
        float inv = 1.f / s;
#pragma unroll
        for (int e = 0; e < E_; e++) r[e] = oma * r[e] * inv + a * g_task_w[bidx][e];

        int i1 = 0; float v1 = r[0];
#pragma unroll
        for (int e = 1; e < E_; e++) if (r[e] > v1) { v1 = r[e]; i1 = e; }
        int i2 = (i1 == 0) ? 1 : 0; float v2 = r[i2];
#pragma unroll
        for (int e = 0; e < E_; e++)
            if (e != i1 && e != i2 && r[e] > v2) { v2 = r[e]; i2 = e; }

        float e2  = expf(v2 - v1);
        float den = 1.f / (1.f + e2);
        float o[E_];
#pragma unroll
        for (int e = 0; e < E_; e++) o[e] = 0.f;
        o[i1] = den;
        o[i2] = e2 * den;
        float4* op = (float4*)(out + (size_t)row * E_);
        op[0] = make_float4(o[0], o[1], o[2], o[3]);
        op[1] = make_float4(o[4], o[5], o[6], o[7]);
    }
}

// ---------------- launch ----------------
extern "C" void kernel_launch(void* const* d_in, const int* in_sizes, int n_in,
                              void* d_out, int out_size) {
    const float* X     = (const float*)d_in[0];
    const float* task  = (const float*)d_in[1];
    const float* W1    = (const float*)d_in[2];
    const float* b1    = (const float*)d_in[3];
    const float* W2    = (const float*)d_in[4];
    const float* b2    = (const float*)d_in[5];
    const float* TW1   = (const float*)d_in[6];
    const float* Tb1   = (const float*)d_in[7];
    const float* TW2   = (const float*)d_in[8];
    const float* Tb2   = (const float*)d_in[9];
    const float* alpha = (const float*)d_in[10];
    float* out = (float*)d_out;

    cudaFuncSetAttribute(gemm_router_kernel,
                         cudaFuncAttributeMaxDynamicSharedMemorySize, SMEM_BYTES);

    prelude_kernel<<<640, 1024>>>(W1, task, TW1, Tb1, TW2, Tb2, alpha);
    gemm_router_kernel<<<M_ / MTILE, NTH, SMEM_BYTES>>>(X, b1, W2, b2, out);
}